// round 1
// baseline (speedup 1.0000x reference)
#include <cuda_runtime.h>
#include <math.h>

// ---------------- geometry ----------------
// x      : [128,  1, 128, 128]
// h1     : [128, 32,  64,  64]   conv1 k4 s2 p1 + relu
// h2     : [128, 64,  32,  32]   conv2 k4 s2 p1 + relu
// z      : [128, 64,  32,  32]   conv3 k3 s1 p1
// z_q    : [128, 64,  32,  32]   codebook gather (straight-through == z_q)
// d1     : [128, 64,  32,  32]   deconv1 k3 s1 p1 + relu   (reuses h2 buffer)
// d2     : [128, 32,  64,  64]   deconv2 k4 s2 p1 + relu   (reuses h1 buffer)
// x_rec  : [128,  1, 128, 128]   deconv3 k4 s2 p1 + sigmoid -> d_out[0:2097152]
// d_out[2097152] = recon_loss, d_out[2097153] = vq_loss

#define N_XREC   2097152
#define N_Z      8388608   // 128*64*32*32

__device__ float g_h1[128 * 32 * 64 * 64];   // also reused for d2
__device__ float g_h2[128 * 64 * 32 * 32];   // also reused for d1
__device__ float g_z [128 * 64 * 32 * 32];
__device__ float g_zq[128 * 64 * 32 * 32];

// ---------------- init ----------------
__global__ void zero_losses_k(float* out) {
    if (threadIdx.x == 0) { out[N_XREC] = 0.0f; out[N_XREC + 1] = 0.0f; }
}

// ---------------- conv1: 1->32, k4 s2 p1, relu ----------------
__global__ void __launch_bounds__(256) conv1_k(const float* __restrict__ x,
                                               const float* __restrict__ w,
                                               const float* __restrict__ b) {
    int idx = blockIdx.x * 256 + threadIdx.x;          // [n,o,y,x] 2^24
    int xo = idx & 63, yo = (idx >> 6) & 63, o = (idx >> 12) & 31, n = idx >> 17;
    __shared__ float ws[512];                          // all 32*1*16 weights
    for (int i = threadIdx.x; i < 512; i += 256) ws[i] = w[i];
    __syncthreads();
    float acc = b[o];
    const float* xin = x + n * 16384;
    int iy0 = 2 * yo - 1, ix0 = 2 * xo - 1;
    const float* wp = ws + o * 16;
#pragma unroll
    for (int ky = 0; ky < 4; ky++) {
        int iy = iy0 + ky;
        if ((unsigned)iy < 128u) {
#pragma unroll
            for (int kx = 0; kx < 4; kx++) {
                int ix = ix0 + kx;
                if ((unsigned)ix < 128u)
                    acc = fmaf(xin[iy * 128 + ix], wp[ky * 4 + kx], acc);
            }
        }
    }
    g_h1[idx] = fmaxf(acc, 0.0f);
}

// ---------------- conv2: 32->64, k4 s2 p1, relu ----------------
__global__ void __launch_bounds__(256) conv2_k(const float* __restrict__ w,
                                               const float* __restrict__ b) {
    int idx = blockIdx.x * 256 + threadIdx.x;          // [n,o,y,x] 2^23
    int xo = idx & 31, yo = (idx >> 5) & 31, o = (idx >> 10) & 63, n = idx >> 16;
    __shared__ float ws[512];                          // w[o, 0:32, 4,4]
    for (int i = threadIdx.x; i < 512; i += 256) ws[i] = w[o * 512 + i];
    __syncthreads();
    float acc = b[o];
    int iy0 = 2 * yo - 1, ix0 = 2 * xo - 1;
    const float* in0 = g_h1 + n * (32 * 4096);
    for (int ci = 0; ci < 32; ci++) {
        const float* inp = in0 + ci * 4096;
        const float* wp  = ws + ci * 16;
#pragma unroll
        for (int ky = 0; ky < 4; ky++) {
            int iy = iy0 + ky;
            if ((unsigned)iy < 64u) {
#pragma unroll
                for (int kx = 0; kx < 4; kx++) {
                    int ix = ix0 + kx;
                    if ((unsigned)ix < 64u)
                        acc = fmaf(inp[iy * 64 + ix], wp[ky * 4 + kx], acc);
                }
            }
        }
    }
    g_h2[idx] = fmaxf(acc, 0.0f);
}

// ---------------- conv3: 64->64, k3 s1 p1, no relu ----------------
__global__ void __launch_bounds__(256) conv3_k(const float* __restrict__ w,
                                               const float* __restrict__ b) {
    int idx = blockIdx.x * 256 + threadIdx.x;          // [n,o,y,x] 2^23
    int xo = idx & 31, yo = (idx >> 5) & 31, o = (idx >> 10) & 63, n = idx >> 16;
    __shared__ float ws[576];                          // w[o, 0:64, 3,3]
    for (int i = threadIdx.x; i < 576; i += 256) ws[i] = w[o * 576 + i];
    __syncthreads();
    float acc = b[o];
    int iy0 = yo - 1, ix0 = xo - 1;
    const float* in0 = g_h2 + n * (64 * 1024);
    for (int ci = 0; ci < 64; ci++) {
        const float* inp = in0 + ci * 1024;
        const float* wp  = ws + ci * 9;
#pragma unroll
        for (int ky = 0; ky < 3; ky++) {
            int iy = iy0 + ky;
            if ((unsigned)iy < 32u) {
#pragma unroll
                for (int kx = 0; kx < 3; kx++) {
                    int ix = ix0 + kx;
                    if ((unsigned)ix < 32u)
                        acc = fmaf(inp[iy * 32 + ix], wp[ky * 3 + kx], acc);
                }
            }
        }
    }
    g_z[idx] = acc;
}

// ---------------- quantize: argmin over 128 codes, dim 64 ----------------
__global__ void __launch_bounds__(256) quantize_k(const float* __restrict__ cb,
                                                  float* out) {
    __shared__ float cbs[8192];   // 128 x 64 codebook
    __shared__ float cn[128];     // per-code squared norms
    __shared__ float red[256];
    int t = threadIdx.x;
    for (int i = t; i < 8192; i += 256) cbs[i] = cb[i];
    __syncthreads();
    if (t < 128) {
        float s = 0.0f;
        const float* cp = cbs + t * 64;
#pragma unroll
        for (int d = 0; d < 64; d++) s = fmaf(cp[d], cp[d], s);
        cn[t] = s;
    }
    __syncthreads();

    int p = blockIdx.x * 256 + t;            // position in [0, 131072)
    int hw = p & 1023, n = p >> 10;
    const float* zp = g_z + n * 65536 + hw;  // d-stride = 1024
    float zr[64];
#pragma unroll
    for (int d = 0; d < 64; d++) zr[d] = zp[d * 1024];

    int best = 0;
    float bestv = 3.4e38f;
    for (int e = 0; e < 128; e++) {
        const float* cp = cbs + e * 64;
        float dot = 0.0f;
#pragma unroll
        for (int d = 0; d < 64; d++) dot = fmaf(zr[d], cp[d], dot);
        float sc = cn[e] - 2.0f * dot;       // same ordering as ref d2
        if (sc < bestv) { bestv = sc; best = e; }
    }

    float vs = 0.0f;
    float* zqp = g_zq + n * 65536 + hw;
    const float* cbest = cbs + best * 64;
#pragma unroll
    for (int d = 0; d < 64; d++) {
        float c = cbest[d];
        zqp[d * 1024] = c;
        float df = zr[d] - c;
        vs = fmaf(df, df, vs);
    }

    red[t] = vs;
    __syncthreads();
    for (int s = 128; s > 0; s >>= 1) {
        if (t < s) red[t] += red[t + s];
        __syncthreads();
    }
    if (t == 0) atomicAdd(out + N_XREC + 1, red[0] * (1.0f / (float)N_Z));
}

// ---------------- deconv1: 64->64, k3 s1 p1, relu ----------------
// out[n,o,y,x] = b + sum_i sum_{ky,kx} zq[n,i,y+1-ky,x+1-kx] * w[i,o,ky,kx]
__global__ void __launch_bounds__(256) deconv1_k(const float* __restrict__ w,
                                                 const float* __restrict__ b) {
    int idx = blockIdx.x * 256 + threadIdx.x;          // [n,o,y,x] 2^23
    int xo = idx & 31, yo = (idx >> 5) & 31, o = (idx >> 10) & 63, n = idx >> 16;
    __shared__ float ws[576];                          // w[i, o, ky, kx], i-major
    for (int j = threadIdx.x; j < 576; j += 256) {
        int i = j / 9, tap = j - i * 9;
        ws[j] = w[(i * 64 + o) * 9 + tap];
    }
    __syncthreads();
    float acc = b[o];
    const float* in0 = g_zq + n * (64 * 1024);
    for (int i = 0; i < 64; i++) {
        const float* inp = in0 + i * 1024;
        const float* wp  = ws + i * 9;
#pragma unroll
        for (int ky = 0; ky < 3; ky++) {
            int iy = yo + 1 - ky;
            if ((unsigned)iy < 32u) {
#pragma unroll
                for (int kx = 0; kx < 3; kx++) {
                    int ix = xo + 1 - kx;
                    if ((unsigned)ix < 32u)
                        acc = fmaf(inp[iy * 32 + ix], wp[ky * 3 + kx], acc);
                }
            }
        }
    }
    g_h2[idx] = fmaxf(acc, 0.0f);   // reuse buffer as d1
}

// ---------------- deconv2: 64->32, k4 s2 p1, relu ----------------
// yi = (y+1-ky)/2 must be integer: ky in {ky0, ky0+2}, ky0 = (y+1)&1
__global__ void __launch_bounds__(256) deconv2_k(const float* __restrict__ w,
                                                 const float* __restrict__ b) {
    int idx = blockIdx.x * 256 + threadIdx.x;          // [n,o,y,x] 2^24
    int xo = idx & 63, yo = (idx >> 6) & 63, o = (idx >> 12) & 31, n = idx >> 17;
    __shared__ float ws[1024];                         // w[i, o, 4,4], i in [0,64)
    for (int j = threadIdx.x; j < 1024; j += 256) {
        int i = j >> 4, tap = j & 15;
        ws[j] = w[(i * 32 + o) * 16 + tap];
    }
    __syncthreads();
    float acc = b[o];
    int ky0 = (yo + 1) & 1, kx0 = (xo + 1) & 1;
    int yiA = (yo + 1 - ky0) >> 1, xiA = (xo + 1 - kx0) >> 1;
    int yiB = yiA - 1, xiB = xiA - 1;
    bool vyA = yiA < 32, vyB = yiB >= 0, vxA = xiA < 32, vxB = xiB >= 0;
    int tAA = ky0 * 4 + kx0, tAB = ky0 * 4 + kx0 + 2;
    int tBA = (ky0 + 2) * 4 + kx0, tBB = (ky0 + 2) * 4 + kx0 + 2;
    const float* in0 = g_h2 + n * (64 * 1024);
    for (int i = 0; i < 64; i++) {
        const float* inp = in0 + i * 1024;
        const float* wp  = ws + i * 16;
        if (vyA && vxA) acc = fmaf(inp[yiA * 32 + xiA], wp[tAA], acc);
        if (vyA && vxB) acc = fmaf(inp[yiA * 32 + xiB], wp[tAB], acc);
        if (vyB && vxA) acc = fmaf(inp[yiB * 32 + xiA], wp[tBA], acc);
        if (vyB && vxB) acc = fmaf(inp[yiB * 32 + xiB], wp[tBB], acc);
    }
    g_h1[idx] = fmaxf(acc, 0.0f);   // reuse buffer as d2
}

// ---------------- deconv3: 32->1, k4 s2 p1, sigmoid + recon loss ----------------
__global__ void __launch_bounds__(256) deconv3_k(const float* __restrict__ xin,
                                                 const float* __restrict__ w,
                                                 const float* __restrict__ b,
                                                 float* out) {
    int idx = blockIdx.x * 256 + threadIdx.x;          // [n,y,x] 2^21
    int xo = idx & 127, yo = (idx >> 7) & 127, n = idx >> 14;
    __shared__ float ws[512];                          // w[i, 0, 4,4], contiguous
    __shared__ float red[256];
    for (int j = threadIdx.x; j < 512; j += 256) ws[j] = w[j];
    __syncthreads();
    float acc = b[0];
    int ky0 = (yo + 1) & 1, kx0 = (xo + 1) & 1;
    int yiA = (yo + 1 - ky0) >> 1, xiA = (xo + 1 - kx0) >> 1;
    int yiB = yiA - 1, xiB = xiA - 1;
    bool vyA = yiA < 64, vyB = yiB >= 0, vxA = xiA < 64, vxB = xiB >= 0;
    int tAA = ky0 * 4 + kx0, tAB = ky0 * 4 + kx0 + 2;
    int tBA = (ky0 + 2) * 4 + kx0, tBB = (ky0 + 2) * 4 + kx0 + 2;
    const float* in0 = g_h1 + n * (32 * 4096);
    for (int i = 0; i < 32; i++) {
        const float* inp = in0 + i * 4096;
        const float* wp  = ws + i * 16;
        if (vyA && vxA) acc = fmaf(inp[yiA * 64 + xiA], wp[tAA], acc);
        if (vyA && vxB) acc = fmaf(inp[yiA * 64 + xiB], wp[tAB], acc);
        if (vyB && vxA) acc = fmaf(inp[yiB * 64 + xiA], wp[tBA], acc);
        if (vyB && vxB) acc = fmaf(inp[yiB * 64 + xiB], wp[tBB], acc);
    }
    float r = 1.0f / (1.0f + expf(-acc));
    out[idx] = r;
    float df = r - xin[idx];

    red[threadIdx.x] = df * df;
    __syncthreads();
    for (int s = 128; s > 0; s >>= 1) {
        if (threadIdx.x < s) red[threadIdx.x] += red[threadIdx.x + s];
        __syncthreads();
    }
    if (threadIdx.x == 0)
        atomicAdd(out + N_XREC, red[0] * (1.0f / (float)N_XREC));
}

// ---------------- launch ----------------
extern "C" void kernel_launch(void* const* d_in, const int* in_sizes, int n_in,
                              void* d_out, int out_size) {
    const float* x   = (const float*)d_in[0];
    const float* w1  = (const float*)d_in[1];
    const float* b1  = (const float*)d_in[2];
    const float* w2  = (const float*)d_in[3];
    const float* b2  = (const float*)d_in[4];
    const float* w3  = (const float*)d_in[5];
    const float* b3  = (const float*)d_in[6];
    const float* cb  = (const float*)d_in[7];
    const float* dw1 = (const float*)d_in[8];
    const float* db1 = (const float*)d_in[9];
    const float* dw2 = (const float*)d_in[10];
    const float* db2 = (const float*)d_in[11];
    const float* dw3 = (const float*)d_in[12];
    const float* db3 = (const float*)d_in[13];
    float* out = (float*)d_out;

    zero_losses_k<<<1, 32>>>(out);
    conv1_k  <<<65536, 256>>>(x, w1, b1);
    conv2_k  <<<32768, 256>>>(w2, b2);
    conv3_k  <<<32768, 256>>>(w3, b3);
    quantize_k<<<512,  256>>>(cb, out);
    deconv1_k<<<32768, 256>>>(dw1, db1);
    deconv2_k<<<65536, 256>>>(dw2, db2);
    deconv3_k<<<8192,  256>>>(x, dw3, db3, out);
}

// round 2
// speedup vs baseline: 3.7998x; 3.7998x over previous
#include <cuda_runtime.h>
#include <math.h>

// ---------------- geometry ----------------
// x      : [128,  1, 128, 128]
// h1     : [128, 32,  64,  64]   conv1 k4 s2 p1 + relu        (g_h1, reused for d2)
// h2     : [128, 64,  32,  32]   conv2 k4 s2 p1 + relu        (g_h2, reused for d1)
// z      : [128, 64,  32,  32]   conv3 k3 s1 p1               (g_z)
// z_q    : [128, 64,  32,  32]   codebook gather              (g_zq)
// x_rec  : [128,  1, 128, 128]   -> d_out[0 : 2097152]
// d_out[2097152] = recon_loss, d_out[2097153] = vq_loss

#define N_XREC   2097152
#define N_Z      8388608

__device__ float g_h1[128 * 32 * 64 * 64];
__device__ float g_h2[128 * 64 * 32 * 32];
__device__ float g_z [128 * 64 * 32 * 32];
__device__ float g_zq[128 * 64 * 32 * 32];

__global__ void zero_losses_k(float* out) {
    if (threadIdx.x == 0) { out[N_XREC] = 0.0f; out[N_XREC + 1] = 0.0f; }
}

// ---------------- conv1: 1->32, k4 s2 p1, relu ----------------
// 1 thread = 1 spatial position, all 32 output channels (16 input regs reused 32x)
__global__ void __launch_bounds__(256) conv1_k(const float* __restrict__ x,
                                               const float* __restrict__ w,
                                               const float* __restrict__ b) {
    __shared__ float ws[512];
    __shared__ float bs[32];
    int n = blockIdx.x >> 4, y0 = (blockIdx.x & 15) * 4;
    int t = threadIdx.x;
    int xo = t & 63, yo = y0 + (t >> 6);
    for (int i = t; i < 512; i += 256) ws[i] = w[i];
    if (t < 32) bs[t] = b[t];
    __syncthreads();

    float xin[16];
    const float* xp = x + n * 16384;
    int iy0 = 2 * yo - 1, ix0 = 2 * xo - 1;
#pragma unroll
    for (int ky = 0; ky < 4; ky++) {
        int iy = iy0 + ky;
#pragma unroll
        for (int kx = 0; kx < 4; kx++) {
            int ix = ix0 + kx;
            xin[ky * 4 + kx] = ((unsigned)iy < 128u && (unsigned)ix < 128u)
                               ? xp[iy * 128 + ix] : 0.0f;
        }
    }
    float* outp = g_h1 + n * 131072 + yo * 64 + xo;
#pragma unroll 4
    for (int o = 0; o < 32; o++) {
        float acc = bs[o];
#pragma unroll
        for (int k = 0; k < 16; k++) acc = fmaf(xin[k], ws[o * 16 + k], acc);
        outp[o * 4096] = fmaxf(acc, 0.0f);
    }
}

// ---------------- conv2: 32->64, k4 s2 p1, relu (tiled) ----------------
// block: 1 image, 64 o, spatial 32x * 4y. thread: 4 o * 8 x.
__global__ void __launch_bounds__(256) conv2t_k(const float* __restrict__ w,
                                                const float* __restrict__ b) {
    __shared__ float tin[4][10][67];   // ci-chunk, padded input tile
    __shared__ float ws[4][64][16];
    int n = blockIdx.x >> 3, y0 = (blockIdx.x & 7) * 4;
    int t = threadIdx.x;
    int obase = (t >> 4) * 4;
    int sslot = t & 15;
    int ys = sslot >> 2, x0 = (sslot & 3) * 8;

    float acc[4][8];
#pragma unroll
    for (int j = 0; j < 4; j++)
#pragma unroll
        for (int s = 0; s < 8; s++) acc[j][s] = 0.0f;

    const float* in0 = g_h1 + n * 131072;
    for (int ch = 0; ch < 8; ch++) {          // 8 chunks of 4 ci
        __syncthreads();
        for (int j = t; j < 4 * 64 * 16; j += 256) {   // ws[cc][o][tap]
            int cc = j >> 10, rem = j & 1023, o = rem >> 4, tap = rem & 15;
            ws[cc][o][tap] = w[(o * 32 + ch * 4 + cc) * 16 + tap];
        }
        for (int j = t; j < 4 * 10 * 66; j += 256) {   // tin[cc][r][c]
            int cc = j / 660, rem = j - cc * 660, r = rem / 66, c = rem - r * 66;
            int iy = 2 * y0 - 1 + r, ix = c - 1;
            float v = 0.0f;
            if ((unsigned)iy < 64u && (unsigned)ix < 64u)
                v = in0[(ch * 4 + cc) * 4096 + iy * 64 + ix];
            tin[cc][r][c] = v;
        }
        __syncthreads();
#pragma unroll
        for (int cc = 0; cc < 4; cc++) {
#pragma unroll
            for (int ky = 0; ky < 4; ky++) {
                float xr[18];
#pragma unroll
                for (int c = 0; c < 18; c++) xr[c] = tin[cc][2 * ys + ky][2 * x0 + c];
#pragma unroll
                for (int j = 0; j < 4; j++) {
                    float w0 = ws[cc][obase + j][ky * 4 + 0];
                    float w1 = ws[cc][obase + j][ky * 4 + 1];
                    float w2 = ws[cc][obase + j][ky * 4 + 2];
                    float w3 = ws[cc][obase + j][ky * 4 + 3];
#pragma unroll
                    for (int s = 0; s < 8; s++) {
                        float a = acc[j][s];
                        a = fmaf(xr[2 * s + 0], w0, a);
                        a = fmaf(xr[2 * s + 1], w1, a);
                        a = fmaf(xr[2 * s + 2], w2, a);
                        a = fmaf(xr[2 * s + 3], w3, a);
                        acc[j][s] = a;
                    }
                }
            }
        }
    }
    float* out0 = g_h2 + n * 65536 + (y0 + ys) * 32 + x0;
#pragma unroll
    for (int j = 0; j < 4; j++) {
        float bv = b[obase + j];
#pragma unroll
        for (int s = 0; s < 8; s++)
            out0[(obase + j) * 1024 + s] = fmaxf(acc[j][s] + bv, 0.0f);
    }
}

// ---------------- conv3 / deconv1 shared body: 64->64, k3 s1 p1 ----------------
// FLIP=0: conv (w [o][i][9], input g_h2, out g_z, no relu)
// FLIP=1: deconv (w [i][o][9] tap-flipped, input g_zq, out g_h2, relu)
template <int FLIP>
__global__ void __launch_bounds__(256) conv3x3_k(const float* __restrict__ w,
                                                 const float* __restrict__ b) {
    __shared__ float tin[8][6][35];
    __shared__ float ws[8][64][9];
    int n = blockIdx.x >> 3, y0 = (blockIdx.x & 7) * 4;
    int t = threadIdx.x;
    int obase = (t >> 4) * 4;
    int sslot = t & 15;
    int ys = sslot >> 2, x0 = (sslot & 3) * 8;

    float acc[4][8];
#pragma unroll
    for (int j = 0; j < 4; j++)
#pragma unroll
        for (int s = 0; s < 8; s++) acc[j][s] = 0.0f;

    const float* in0 = (FLIP ? g_zq : g_h2) + n * 65536;
    for (int ch = 0; ch < 8; ch++) {          // 8 chunks of 8 ci
        __syncthreads();
        for (int j = t; j < 8 * 64 * 9; j += 256) {    // ws[cc][o][tap]
            int cc = j / 576, rem = j - cc * 576, o = rem / 9, tap = rem - o * 9;
            int ci = ch * 8 + cc;
            if (FLIP) ws[cc][o][tap] = w[(ci * 64 + o) * 9 + (8 - tap)];
            else      ws[cc][o][tap] = w[(o * 64 + ci) * 9 + tap];
        }
        for (int j = t; j < 8 * 6 * 34; j += 256) {    // tin[cc][r][c]
            int cc = j / 204, rem = j - cc * 204, r = rem / 34, c = rem - r * 34;
            int iy = y0 - 1 + r, ix = c - 1;
            float v = 0.0f;
            if ((unsigned)iy < 32u && (unsigned)ix < 32u)
                v = in0[(ch * 8 + cc) * 1024 + iy * 32 + ix];
            tin[cc][r][c] = v;
        }
        __syncthreads();
#pragma unroll 2
        for (int cc = 0; cc < 8; cc++) {
#pragma unroll
            for (int ky = 0; ky < 3; ky++) {
                float xr[10];
#pragma unroll
                for (int c = 0; c < 10; c++) xr[c] = tin[cc][ys + ky][x0 + c];
#pragma unroll
                for (int j = 0; j < 4; j++) {
                    float w0 = ws[cc][obase + j][ky * 3 + 0];
                    float w1 = ws[cc][obase + j][ky * 3 + 1];
                    float w2 = ws[cc][obase + j][ky * 3 + 2];
#pragma unroll
                    for (int s = 0; s < 8; s++) {
                        float a = acc[j][s];
                        a = fmaf(xr[s + 0], w0, a);
                        a = fmaf(xr[s + 1], w1, a);
                        a = fmaf(xr[s + 2], w2, a);
                        acc[j][s] = a;
                    }
                }
            }
        }
    }
    float* out0 = (FLIP ? g_h2 : g_z) + n * 65536 + (y0 + ys) * 32 + x0;
#pragma unroll
    for (int j = 0; j < 4; j++) {
        float bv = b[obase + j];
#pragma unroll
        for (int s = 0; s < 8; s++) {
            float v = acc[j][s] + bv;
            out0[(obase + j) * 1024 + s] = FLIP ? fmaxf(v, 0.0f) : v;
        }
    }
}

// ---------------- quantize: argmin over 128 codes, dim 64 ----------------
__global__ void __launch_bounds__(256) quantize_k(const float* __restrict__ cb,
                                                  float* out) {
    __shared__ float4 cbs[2048];   // 128 x 64 codebook, float4
    __shared__ float cn[128];
    __shared__ float red[256];
    int t = threadIdx.x;
    for (int i = t; i < 2048; i += 256) cbs[i] = ((const float4*)cb)[i];
    __syncthreads();
    if (t < 128) {
        float s = 0.0f;
        const float4* cp = cbs + t * 16;
#pragma unroll
        for (int d = 0; d < 16; d++) {
            float4 c = cp[d];
            s = fmaf(c.x, c.x, s); s = fmaf(c.y, c.y, s);
            s = fmaf(c.z, c.z, s); s = fmaf(c.w, c.w, s);
        }
        cn[t] = s;
    }
    __syncthreads();

    int p = blockIdx.x * 256 + t;
    int hw = p & 1023, n = p >> 10;
    const float* zp = g_z + n * 65536 + hw;
    float zr[64];
#pragma unroll
    for (int d = 0; d < 64; d++) zr[d] = zp[d * 1024];

    int best = 0;
    float bestv = 3.4e38f;
    for (int e = 0; e < 128; e++) {
        const float4* cp = cbs + e * 16;
        float dot = 0.0f;
#pragma unroll
        for (int d = 0; d < 16; d++) {
            float4 c = cp[d];
            dot = fmaf(zr[4 * d + 0], c.x, dot);
            dot = fmaf(zr[4 * d + 1], c.y, dot);
            dot = fmaf(zr[4 * d + 2], c.z, dot);
            dot = fmaf(zr[4 * d + 3], c.w, dot);
        }
        float sc = cn[e] - 2.0f * dot;
        if (sc < bestv) { bestv = sc; best = e; }
    }

    float vs = 0.0f;
    float* zqp = g_zq + n * 65536 + hw;
    const float* cbest = (const float*)(cbs + best * 16);
#pragma unroll
    for (int d = 0; d < 64; d++) {
        float c = cbest[d];
        zqp[d * 1024] = c;
        float df = zr[d] - c;
        vs = fmaf(df, df, vs);
    }

    red[t] = vs;
    __syncthreads();
    for (int s = 128; s > 0; s >>= 1) {
        if (t < s) red[t] += red[t + s];
        __syncthreads();
    }
    if (t == 0) atomicAdd(out + N_XREC + 1, red[0] * (1.0f / (float)N_Z));
}

// ---------------- deconv2: 64->32, k4 s2 p1, relu (tiled) ----------------
// block: 1 image, 32 o, spatial 64x * 4y. thread: 4 o * 8 x.
__global__ void __launch_bounds__(256) deconv2t_k(const float* __restrict__ w,
                                                  const float* __restrict__ b) {
    __shared__ float tin[8][4][35];
    __shared__ float ws[8 * 32 * 16];  // [cc][o][tap], ci-major == global layout
    int n = blockIdx.x >> 4, y0 = (blockIdx.x & 15) * 4;
    int t = threadIdx.x;
    int obase = (t >> 5) * 4;
    int sslot = t & 31;
    int ys = sslot >> 3, x0 = (sslot & 7) * 8;

    int yo = y0 + ys;
    int ky0 = (yo + 1) & 1;
    int yiA = (yo + 1 - ky0) >> 1;
    int rowA = yiA - (y0 >> 1) + 1;     // in [1,3]
    int rowB = rowA - 1;
    int cbase = x0 >> 1;

    float acc[4][8];
#pragma unroll
    for (int j = 0; j < 4; j++)
#pragma unroll
        for (int s = 0; s < 8; s++) acc[j][s] = 0.0f;

    const float* in0 = g_h2 + n * 65536;
    for (int ch = 0; ch < 8; ch++) {          // 8 chunks of 8 ci
        __syncthreads();
        for (int j = t; j < 4096; j += 256)   // contiguous [ci][o][16]
            ws[j] = w[ch * 4096 + j];
        for (int j = t; j < 8 * 4 * 34; j += 256) {
            int cc = j / 136, rem = j - cc * 136, r = rem / 34, c = rem - r * 34;
            int yi = (y0 >> 1) - 1 + r, xi = c - 1;
            float v = 0.0f;
            if ((unsigned)yi < 32u && (unsigned)xi < 32u)
                v = in0[(ch * 8 + cc) * 1024 + yi * 32 + xi];
            tin[cc][r][c] = v;
        }
        __syncthreads();
#pragma unroll 2
        for (int cc = 0; cc < 8; cc++) {
            float a[6], bb[6];
#pragma unroll
            for (int c = 0; c < 6; c++) {
                a[c]  = tin[cc][rowA][cbase + c];
                bb[c] = tin[cc][rowB][cbase + c];
            }
#pragma unroll
            for (int j = 0; j < 4; j++) {
                const float* wp = ws + cc * 512 + (obase + j) * 16;
                float wk0 = wp[ky0 * 4 + 0], wk1 = wp[ky0 * 4 + 1];
                float wk2 = wp[ky0 * 4 + 2], wk3 = wp[ky0 * 4 + 3];
                float wk4 = wp[(ky0 + 2) * 4 + 0], wk5 = wp[(ky0 + 2) * 4 + 1];
                float wk6 = wp[(ky0 + 2) * 4 + 2], wk7 = wp[(ky0 + 2) * 4 + 3];
#pragma unroll
                for (int s = 0; s < 8; s++) {
                    int ia = (s >> 1) + (s & 1) + 1, ib = ia - 1;
                    float v = acc[j][s];
                    if (s & 1) {   // kx0 = 0
                        v = fmaf(a[ia],  wk0, v);
                        v = fmaf(a[ib],  wk2, v);
                        v = fmaf(bb[ia], wk4, v);
                        v = fmaf(bb[ib], wk6, v);
                    } else {       // kx0 = 1
                        v = fmaf(a[ia],  wk1, v);
                        v = fmaf(a[ib],  wk3, v);
                        v = fmaf(bb[ia], wk5, v);
                        v = fmaf(bb[ib], wk7, v);
                    }
                    acc[j][s] = v;
                }
            }
        }
    }
    float* out0 = g_h1 + n * 131072 + yo * 64 + x0;
#pragma unroll
    for (int j = 0; j < 4; j++) {
        float bv = b[obase + j];
#pragma unroll
        for (int s = 0; s < 8; s++)
            out0[(obase + j) * 4096 + s] = fmaxf(acc[j][s] + bv, 0.0f);
    }
}

// ---------------- deconv3: 32->1, k4 s2 p1, sigmoid + recon loss ----------------
// block: 1 image, spatial 128x * 16y. thread: 8 contiguous x.
__global__ void __launch_bounds__(256) deconv3t_k(const float* __restrict__ xin,
                                                  const float* __restrict__ w,
                                                  const float* __restrict__ b,
                                                  float* out) {
    __shared__ float tin[8][10][66];
    __shared__ float ws3[512];
    __shared__ float red[256];
    int n = blockIdx.x >> 3, y0 = (blockIdx.x & 7) * 16;
    int t = threadIdx.x;
    int ys = t >> 4, x0 = (t & 15) * 8;
    int yo = y0 + ys;
    int ky0 = (yo + 1) & 1;
    int yiA = (yo + 1 - ky0) >> 1;
    int rowA = yiA - (y0 >> 1) + 1;     // in [1,9]
    int rowB = rowA - 1;
    int cbase = x0 >> 1;

    for (int j = t; j < 512; j += 256) ws3[j] = w[j];

    float acc[8];
#pragma unroll
    for (int s = 0; s < 8; s++) acc[s] = 0.0f;

    const float* in0 = g_h1 + n * 131072;
    for (int ch = 0; ch < 4; ch++) {          // 4 chunks of 8 ci
        __syncthreads();
        for (int j = t; j < 8 * 10 * 66; j += 256) {
            int cc = j / 660, rem = j - cc * 660, r = rem / 66, c = rem - r * 66;
            int yi = (y0 >> 1) - 1 + r, xi = c - 1;
            float v = 0.0f;
            if ((unsigned)yi < 64u && (unsigned)xi < 64u)
                v = in0[(ch * 8 + cc) * 4096 + yi * 64 + xi];
            tin[cc][r][c] = v;
        }
        __syncthreads();
#pragma unroll 2
        for (int cc = 0; cc < 8; cc++) {
            float a[6], bb[6];
#pragma unroll
            for (int c = 0; c < 6; c++) {
                a[c]  = tin[cc][rowA][cbase + c];
                bb[c] = tin[cc][rowB][cbase + c];
            }
            const float* wp = ws3 + (ch * 8 + cc) * 16;
            float wk0 = wp[ky0 * 4 + 0], wk1 = wp[ky0 * 4 + 1];
            float wk2 = wp[ky0 * 4 + 2], wk3 = wp[ky0 * 4 + 3];
            float wk4 = wp[(ky0 + 2) * 4 + 0], wk5 = wp[(ky0 + 2) * 4 + 1];
            float wk6 = wp[(ky0 + 2) * 4 + 2], wk7 = wp[(ky0 + 2) * 4 + 3];
#pragma unroll
            for (int s = 0; s < 8; s++) {
                int ia = (s >> 1) + (s & 1) + 1, ib = ia - 1;
                float v = acc[s];
                if (s & 1) {
                    v = fmaf(a[ia],  wk0, v);
                    v = fmaf(a[ib],  wk2, v);
                    v = fmaf(bb[ia], wk4, v);
                    v = fmaf(bb[ib], wk6, v);
                } else {
                    v = fmaf(a[ia],  wk1, v);
                    v = fmaf(a[ib],  wk3, v);
                    v = fmaf(bb[ia], wk5, v);
                    v = fmaf(bb[ib], wk7, v);
                }
                acc[s] = v;
            }
        }
    }

    float b0 = b[0];
    const float* xp = xin + n * 16384 + yo * 128 + x0;
    float* op = out + n * 16384 + yo * 128 + x0;
    float ls = 0.0f;
#pragma unroll
    for (int s = 0; s < 8; s++) {
        float r = 1.0f / (1.0f + expf(-(acc[s] + b0)));
        op[s] = r;
        float df = r - xp[s];
        ls = fmaf(df, df, ls);
    }
    red[t] = ls;
    __syncthreads();
    for (int s = 128; s > 0; s >>= 1) {
        if (t < s) red[t] += red[t + s];
        __syncthreads();
    }
    if (t == 0) atomicAdd(out + N_XREC, red[0] * (1.0f / (float)N_XREC));
}

// ---------------- launch ----------------
extern "C" void kernel_launch(void* const* d_in, const int* in_sizes, int n_in,
                              void* d_out, int out_size) {
    const float* x   = (const float*)d_in[0];
    const float* w1  = (const float*)d_in[1];
    const float* b1  = (const float*)d_in[2];
    const float* w2  = (const float*)d_in[3];
    const float* b2  = (const float*)d_in[4];
    const float* w3  = (const float*)d_in[5];
    const float* b3  = (const float*)d_in[6];
    const float* cb  = (const float*)d_in[7];
    const float* dw1 = (const float*)d_in[8];
    const float* db1 = (const float*)d_in[9];
    const float* dw2 = (const float*)d_in[10];
    const float* db2 = (const float*)d_in[11];
    const float* dw3 = (const float*)d_in[12];
    const float* db3 = (const float*)d_in[13];
    float* out = (float*)d_out;

    zero_losses_k<<<1, 32>>>(out);
    conv1_k   <<<2048, 256>>>(x, w1, b1);
    conv2t_k  <<<1024, 256>>>(w2, b2);
    conv3x3_k<0><<<1024, 256>>>(w3, b3);
    quantize_k<<<512,  256>>>(cb, out);
    conv3x3_k<1><<<1024, 256>>>(dw1, db1);
    deconv2t_k<<<2048, 256>>>(dw2, db2);
    deconv3t_k<<<1024, 256>>>(x, dw3, db3, out);
}